// round 6
// baseline (speedup 1.0000x reference)
#include <cuda_runtime.h>
#include <cuda_fp16.h>
#include <math.h>
#include <stdint.h>

// ---------------------------------------------------------------- constants
#define N_TOK 16384
#define NE    4096
#define ED    64
#define BM    128          // tokens per CTA
#define BN    128          // codes per chunk
#define NCH   (NE/BN)      // 32
#define NBLK  (N_TOK/BM)   // 128
#define NTHR  512
#define EPSW  4.0e-5f      // ref fp32 reorder slack + dropped z*e_lo term

#define OUT_ZQ_OFF   1
#define OUT_IDX_OFF  (1 + (size_t)N_TOK*ED)
#define OUT_PERP_OFF (OUT_IDX_OFF + N_TOK)

// SMEM layout of vq_main
#define OFF_A    0                 // zh 16K + zl 16K
#define OFF_B    32768             // 2 bufs x 16K (eh only)
#define OFF_SES  65536             // 16K fp32 ||e||^2
#define SMEM_MAIN (OFF_SES + NE*4) // 81920

// ---------------------------------------------------------------- scratch
__device__ __align__(16) __half d_zh[N_TOK*ED];   // hi(-2z)
__device__ __align__(16) __half d_zl[N_TOK*ED];   // lo(-2z)
__device__ __align__(16) __half d_eh[NE*ED];      // hi(e)
__device__ float d_sz[N_TOK];
__device__ float d_se[NE];
__device__ int   d_counts[NE];
__device__ float d_losstok[N_TOK];
__device__ float d_bd[(size_t)N_TOK*16];          // 16 candidates / token
__device__ int   d_bi[(size_t)N_TOK*16];

// ---------------------------------------------------------------- utils
static __device__ __forceinline__ uint32_t smem_u32(const void* p) {
    uint32_t a;
    asm("{ .reg .u64 t; cvta.to.shared.u64 t, %1; cvt.u32.u64 %0, t; }"
        : "=r"(a) : "l"(p));
    return a;
}
static __device__ __forceinline__ uint32_t swz(uint32_t o) { return o ^ ((o >> 3) & 0x70); }

static __device__ __forceinline__ void ldsm4(uint32_t& r0, uint32_t& r1,
                                             uint32_t& r2, uint32_t& r3, uint32_t a) {
    asm volatile("ldmatrix.sync.aligned.m8n8.x4.shared.b16 {%0,%1,%2,%3}, [%4];"
                 : "=r"(r0), "=r"(r1), "=r"(r2), "=r"(r3) : "r"(a));
}
static __device__ __forceinline__ void mma_f16(float c[4], const uint32_t a[4],
                                               uint32_t b0, uint32_t b1) {
    asm volatile("mma.sync.aligned.m16n8k16.row.col.f32.f16.f16.f32 "
                 "{%0,%1,%2,%3}, {%4,%5,%6,%7}, {%8,%9}, {%0,%1,%2,%3};"
                 : "+f"(c[0]), "+f"(c[1]), "+f"(c[2]), "+f"(c[3])
                 : "r"(a[0]), "r"(a[1]), "r"(a[2]), "r"(a[3]), "r"(b0), "r"(b1));
}
#define CP_ASYNC16(s, g) \
    asm volatile("cp.async.cg.shared.global [%0], [%1], 16;" :: "r"(s), "l"(g))
#define CP_COMMIT() asm volatile("cp.async.commit_group;" ::: "memory")
#define CP_WAIT(n)  asm volatile("cp.async.wait_group %0;" :: "n"(n) : "memory")

// branchless best-2 (values + indices); strict < keeps first index on ties,
// values processed in increasing-k order.
#define UPD2(v0, i0, v1, i1, dv, kk) do { \
    bool _p0 = (dv) < (v0); \
    bool _p1 = (dv) < (v1); \
    (v1) = _p0 ? (v0) : (_p1 ? (dv) : (v1)); \
    (i1) = _p0 ? (i0) : (_p1 ? (kk) : (i1)); \
    (v0) = _p0 ? (dv) : (v0); \
    (i0) = _p0 ? (kk) : (i0); \
} while (0)

// ---------------------------------------------------------------- L1: prep
__global__ void __launch_bounds__(256) vq_prep(const float* __restrict__ z,
                                               const float* __restrict__ cb) {
    int b = blockIdx.x, tid = threadIdx.x;
    int w = tid >> 5, lane = tid & 31;
    int row = b * 8 + w;
    bool isz = row < N_TOK;
    const float* src = isz ? z : cb;
    int r = isz ? row : row - N_TOK;

    float2 v = *(const float2*)&src[(size_t)r * ED + lane * 2];
    float sc = isz ? -2.0f : 1.0f;
    float m0 = sc * v.x, m1 = sc * v.y;
    __half h0 = __float2half_rn(m0), h1 = __float2half_rn(m1);
    __half2 hh; hh.x = h0; hh.y = h1;
    if (isz) {
        float l0 = m0 - __half2float(h0), l1 = m1 - __half2float(h1);
        __half2 ll; ll.x = __float2half_rn(l0); ll.y = __float2half_rn(l1);
        ((__half2*)d_zh)[(size_t)r * 32 + lane] = hh;
        ((__half2*)d_zl)[(size_t)r * 32 + lane] = ll;
    } else {
        ((__half2*)d_eh)[(size_t)r * 32 + lane] = hh;
    }

    float s = __fmaf_rn(v.x, v.x, v.y * v.y);
    #pragma unroll
    for (int o = 16; o; o >>= 1) s += __shfl_xor_sync(0xffffffffu, s, o);
    if (lane == 0) (isz ? d_sz : d_se)[r] = s;
}

// ---------------------------------------------------------------- L2/L3
__global__ void __launch_bounds__(256) vq_zero() {
    int i = blockIdx.x * 256 + threadIdx.x;
    if (i < NE) d_counts[i] = 0;
}
__global__ void __launch_bounds__(256) vq_aux() {
    int i = blockIdx.x * 256 + threadIdx.x;
    if (i < N_TOK) d_losstok[i] = 0.f;
}

// ---------------------------------------------------------------- L4: main
static __device__ __forceinline__ void load_b(uint32_t sb, int ch, int buf) {
    int tid = threadIdx.x;
    size_t k0 = (size_t)ch * BN;
    uint32_t bh = sb + OFF_B + (uint32_t)buf * 16384u;
    #pragma unroll
    for (int p = 0; p < 2; p++) {
        int l = tid + p * NTHR;
        int row = l >> 3, seg = l & 7;
        uint32_t sw = swz((uint32_t)(row * 128 + seg * 16));
        size_t g = ((k0 + row) * ED + seg * 8) * 2;
        CP_ASYNC16(bh + sw, (const char*)d_eh + g);
    }
}

__global__ void __launch_bounds__(NTHR, 1) vq_main() {
    extern __shared__ char smem[];
    uint32_t sb = smem_u32(smem);
    const int tid = threadIdx.x;
    const int w = tid >> 5, lid = tid & 31;
    const int rowgrp = w & 7;       // rows [rowgrp*16, +16)
    const int nhalf = w >> 3;       // chunk codes [nhalf*64, +64)
    const int m0 = blockIdx.x * BM;

    // stage A (zh/zl of -2z) with SW128
    #pragma unroll
    for (int p = 0; p < 2; p++) {
        int l = tid + p * NTHR;
        int row = l >> 3, seg = l & 7;
        uint32_t sw = swz((uint32_t)(row * 128 + seg * 16));
        size_t g = (((size_t)(m0 + row)) * ED + seg * 8) * 2;
        *(uint4*)(smem + OFF_A + sw)         = *(const uint4*)((const char*)d_zh + g);
        *(uint4*)(smem + OFF_A + 16384 + sw) = *(const uint4*)((const char*)d_zl + g);
    }
    float* ses = (float*)(smem + OFF_SES);
    for (int i = tid; i < NE; i += NTHR) ses[i] = d_se[i];
    __syncthreads();

    // A fragments once
    uint32_t ah[4][4], al[4][4];
    {
        int arow = rowgrp * 16 + (lid & 7) + ((lid >> 3) & 1) * 8;
        #pragma unroll
        for (int ks = 0; ks < 4; ks++) {
            uint32_t off = swz((uint32_t)(arow * 128 + ks * 32 + (lid >> 4) * 16));
            ldsm4(ah[ks][0], ah[ks][1], ah[ks][2], ah[ks][3], sb + OFF_A + off);
            ldsm4(al[ks][0], al[ks][1], al[ks][2], al[ks][3], sb + OFF_A + 16384u + off);
        }
    }

    // best-2 per row (rows r0 and r0+8)
    float v00 = 3.4e38f, v01 = 3.4e38f, v10 = 3.4e38f, v11 = 3.4e38f;
    int   i00 = 0x7fffffff, i01 = 0x7fffffff, i10 = 0x7fffffff, i11 = 0x7fffffff;

    load_b(sb, 0, 0);
    CP_COMMIT();

    const int brow_l = (lid & 7) + ((lid >> 3) & 1) * 8;
    const int boff_l = (lid >> 4) * 16;

    for (int ch = 0; ch < NCH; ch++) {
        if (ch + 1 < NCH) { load_b(sb, ch + 1, (ch + 1) & 1); CP_COMMIT(); }
        if (ch + 1 < NCH) CP_WAIT(1); else CP_WAIT(0);
        __syncthreads();

        uint32_t bbase = sb + OFF_B + (uint32_t)((ch & 1) * 16384);

        #pragma unroll
        for (int nt2 = 0; nt2 < 4; nt2++) {
            int codebase = nhalf * 64 + nt2 * 16;
            float aE[4] = {0.f, 0.f, 0.f, 0.f};
            float aO[4] = {0.f, 0.f, 0.f, 0.f};
            #pragma unroll
            for (int ks = 0; ks < 4; ks++) {
                uint32_t sa = swz((uint32_t)((codebase + brow_l) * 128 + ks * 32 + boff_l));
                uint32_t h0, h1, h2, h3;
                ldsm4(h0, h1, h2, h3, bbase + sa);
                mma_f16(aE, ah[ks], h0, h2);   // zh . eh
                mma_f16(aO, ah[ks], h1, h3);
                mma_f16(aE, al[ks], h0, h2);   // zl . eh
                mma_f16(aO, al[ks], h1, h3);
            }
            int cE = codebase + 2 * (lid & 3);
            float2 sE = *(const float2*)&ses[ch * BN + cE];
            float2 sO = *(const float2*)&ses[ch * BN + cE + 8];
            int kg = ch * BN + cE;
            float dv;
            // increasing-k order per row: kg, kg+1, kg+8, kg+9
            dv = __fadd_rn(aE[0], sE.x); UPD2(v00, i00, v01, i01, dv, kg);
            dv = __fadd_rn(aE[1], sE.y); UPD2(v00, i00, v01, i01, dv, kg + 1);
            dv = __fadd_rn(aO[0], sO.x); UPD2(v00, i00, v01, i01, dv, kg + 8);
            dv = __fadd_rn(aO[1], sO.y); UPD2(v00, i00, v01, i01, dv, kg + 9);
            dv = __fadd_rn(aE[2], sE.x); UPD2(v10, i10, v11, i11, dv, kg);
            dv = __fadd_rn(aE[3], sE.y); UPD2(v10, i10, v11, i11, dv, kg + 1);
            dv = __fadd_rn(aO[2], sO.x); UPD2(v10, i10, v11, i11, dv, kg + 8);
            dv = __fadd_rn(aO[3], sO.y); UPD2(v10, i10, v11, i11, dv, kg + 9);
        }
        __syncthreads();
    }

    // store 16 candidates per token: slot = nhalf*8 + (lid&3)*2 + {0,1}
    int t0 = m0 + rowgrp * 16 + (lid >> 2);
    int slot = nhalf * 8 + (lid & 3) * 2;
    size_t b0 = (size_t)t0 * 16 + slot;
    size_t b1 = (size_t)(t0 + 8) * 16 + slot;
    d_bd[b0] = v00; d_bi[b0] = i00; d_bd[b0 + 1] = v01; d_bi[b0 + 1] = i01;
    d_bd[b1] = v10; d_bi[b1] = i10; d_bd[b1 + 1] = v11; d_bi[b1 + 1] = i11;
}

// ---------------------------------------------------------------- L5: resolve
static __device__ __forceinline__ float exact_d(const float* __restrict__ z,
                                                const float* __restrict__ cb,
                                                int t, int ic) {
    const float* zr = z + (size_t)t * ED;
    const float* cr = cb + (size_t)ic * ED;
    float dot = 0.f;
    #pragma unroll
    for (int d = 0; d < ED; d++) dot = __fmaf_rn(zr[d], cr[d], dot);
    return __fmaf_rn(-2.0f, dot, __fadd_rn(d_sz[t], d_se[ic]));
}

__global__ void __launch_bounds__(256) vq_resolve(const float* __restrict__ z,
                                                  const float* __restrict__ cb,
                                                  float* __restrict__ out) {
    int t = (blockIdx.x * 256 + threadIdx.x) >> 5;
    int l = threadIdx.x & 31;

    float v = 3.4e38f; int ix = 0x7fffffff;
    if (l < 16) { v = d_bd[(size_t)t * 16 + l]; ix = d_bi[(size_t)t * 16 + l]; }

    float gv = v; int gi = ix;
    #pragma unroll
    for (int o = 16; o; o >>= 1) {
        float ov = __shfl_xor_sync(0xffffffffu, gv, o);
        int   oi = __shfl_xor_sync(0xffffffffu, gi, o);
        if (ov < gv || (ov == gv && oi < gi)) { gv = ov; gi = oi; }
    }
    float thr = gv + EPSW;

    // odd slots are a thread's 2nd-best: if in-window, a 3rd untracked value
    // could exist in that thread -> full exact scan
    unsigned flagm = __ballot_sync(0xffffffffu, (l < 16) && (l & 1) && (v <= thr));
    unsigned candm = __ballot_sync(0xffffffffu, (l < 16) && (v <= thr));

    int winner;
    if (flagm) {
        float bv = 3.4e38f; int bi_ = 0x7fffffff;
        for (int c = l; c < NE; c += 32) {
            float dv = exact_d(z, cb, t, c);
            if (dv < bv) { bv = dv; bi_ = c; }
        }
        #pragma unroll
        for (int o = 16; o; o >>= 1) {
            float ov = __shfl_xor_sync(0xffffffffu, bv, o);
            int   oi = __shfl_xor_sync(0xffffffffu, bi_, o);
            if (ov < bv || (ov == bv && oi < bi_)) { bv = ov; bi_ = oi; }
        }
        winner = bi_;
    } else if (__popc(candm) > 1) {
        float bv = 3.4e38f; int bi_ = 0x7fffffff;
        if ((l < 16) && (v <= thr)) { bv = exact_d(z, cb, t, ix); bi_ = ix; }
        #pragma unroll
        for (int o = 16; o; o >>= 1) {
            float ov = __shfl_xor_sync(0xffffffffu, bv, o);
            int   oi = __shfl_xor_sync(0xffffffffu, bi_, o);
            if (ov < bv || (ov == bv && oi < bi_)) { bv = ov; bi_ = oi; }
        }
        winner = bi_;
    } else {
        winner = gi;
    }

    if (l == 0) {
        out[OUT_IDX_OFF + t] = (float)winner;
        atomicAdd(&d_counts[winner], 1);
    }

    float lacc = 0.f;
    #pragma unroll
    for (int p = 0; p < 2; p++) {
        int d = l + p * 32;
        float zq = cb[(size_t)winner * ED + d];
        float zv = z[(size_t)t * ED + d];
        float tt = __fsub_rn(zq, zv);
        out[OUT_ZQ_OFF + (size_t)t * ED + d] = __fadd_rn(zv, tt);
        lacc = __fmaf_rn(tt, tt, lacc);
    }
    #pragma unroll
    for (int o = 16; o; o >>= 1) lacc += __shfl_xor_sync(0xffffffffu, lacc, o);
    if (l == 0) d_losstok[t] = lacc;
}

// ---------------------------------------------------------------- L6: finalize
__global__ void __launch_bounds__(1024) vq_finalize(float* __restrict__ out) {
    __shared__ double sh[1024];
    int tid = threadIdx.x;
    double s = 0.0;
    for (int i = tid; i < N_TOK; i += 1024) s += (double)d_losstok[i];
    sh[tid] = s;
    __syncthreads();
    #pragma unroll
    for (int st = 512; st > 0; st >>= 1) {
        if (tid < st) sh[tid] += sh[tid + st];
        __syncthreads();
    }
    if (tid == 0)
        out[0] = (float)(1.25 * sh[0] / (double)((size_t)N_TOK * ED));
    __syncthreads();

    double h = 0.0;
    for (int i = tid; i < NE; i += 1024) {
        float em = (float)d_counts[i] / (float)N_TOK;
        h += (double)(em * logf(em + 1e-10f));
    }
    sh[tid] = h;
    __syncthreads();
    #pragma unroll
    for (int st = 512; st > 0; st >>= 1) {
        if (tid < st) sh[tid] += sh[tid + st];
        __syncthreads();
    }
    if (tid == 0)
        out[OUT_PERP_OFF] = expf(-(float)sh[0]);
}

// ---------------------------------------------------------------- launch
extern "C" void kernel_launch(void* const* d_in, const int* in_sizes, int n_in,
                              void* d_out, int out_size) {
    const float* z  = (const float*)d_in[0];
    const float* cb = (const float*)d_in[1];
    float* out = (float*)d_out;

    cudaFuncSetAttribute(vq_main, cudaFuncAttributeMaxDynamicSharedMemorySize, SMEM_MAIN);

    vq_prep<<<2560, 256>>>(z, cb);         // L1
    vq_zero<<<16, 256>>>();                // L2
    vq_aux<<<64, 256>>>();                 // L3
    vq_main<<<NBLK, NTHR, SMEM_MAIN>>>();  // L4
    vq_resolve<<<N_TOK / 8, 256>>>(z, cb, out);
    vq_finalize<<<1, 1024>>>(out);
}

// round 7
// speedup vs baseline: 2.3841x; 2.3841x over previous
#include <cuda_runtime.h>
#include <cuda_fp16.h>
#include <math.h>
#include <stdint.h>

// ---------------------------------------------------------------- constants
#define N_TOK 16384
#define NE    4096
#define ED    64
#define BM    128          // tokens per CTA
#define BN    128          // codes per chunk
#define NCH   (NE/BN)      // 32
#define NBLK  (N_TOK/BM)   // 128
#define NTHR  512
#define EPSW  3.2e-5f      // 2*(grid slack 7.6e-6 + fp16-e conv err ~6e-6) + margin

#define OUT_ZQ_OFF   1
#define OUT_IDX_OFF  (1 + (size_t)N_TOK*ED)
#define OUT_PERP_OFF (OUT_IDX_OFF + N_TOK)

// SMEM layout of vq_main
#define OFF_A    0                 // zh 16K + zl 16K
#define OFF_B    32768             // 2 bufs x 16K (eh only)
#define OFF_SES  65536             // 16K fp32 ||e||^2
#define SMEM_MAIN (OFF_SES + NE*4) // 81920

// ---------------------------------------------------------------- scratch
__device__ __align__(16) __half d_zh[N_TOK*ED];   // hi(-2z)
__device__ __align__(16) __half d_zl[N_TOK*ED];   // lo(-2z)
__device__ __align__(16) __half d_eh[NE*ED];      // hi(e)
__device__ float d_sz[N_TOK];
__device__ float d_se[NE];
__device__ int   d_counts[NE];
__device__ float d_losstok[N_TOK];
__device__ float d_c2v[(size_t)N_TOK*4];          // best-2 per (token, half)
__device__ int   d_c2i[(size_t)N_TOK*4];
__device__ int   d_win[N_TOK];
__device__ int   d_flag[N_TOK];
__device__ int   d_nflag;

// ---------------------------------------------------------------- utils
static __device__ __forceinline__ uint32_t smem_u32(const void* p) {
    uint32_t a;
    asm("{ .reg .u64 t; cvta.to.shared.u64 t, %1; cvt.u32.u64 %0, t; }"
        : "=r"(a) : "l"(p));
    return a;
}
static __device__ __forceinline__ uint32_t swz(uint32_t o) { return o ^ ((o >> 3) & 0x70); }

static __device__ __forceinline__ void ldsm4(uint32_t& r0, uint32_t& r1,
                                             uint32_t& r2, uint32_t& r3, uint32_t a) {
    asm volatile("ldmatrix.sync.aligned.m8n8.x4.shared.b16 {%0,%1,%2,%3}, [%4];"
                 : "=r"(r0), "=r"(r1), "=r"(r2), "=r"(r3) : "r"(a));
}
static __device__ __forceinline__ void mma_f16(float c[4], const uint32_t a[4],
                                               uint32_t b0, uint32_t b1) {
    asm volatile("mma.sync.aligned.m16n8k16.row.col.f32.f16.f16.f32 "
                 "{%0,%1,%2,%3}, {%4,%5,%6,%7}, {%8,%9}, {%0,%1,%2,%3};"
                 : "+f"(c[0]), "+f"(c[1]), "+f"(c[2]), "+f"(c[3])
                 : "r"(a[0]), "r"(a[1]), "r"(a[2]), "r"(a[3]), "r"(b0), "r"(b1));
}
#define CP_ASYNC16(s, g) \
    asm volatile("cp.async.cg.shared.global [%0], [%1], 16;" :: "r"(s), "l"(g))
#define CP_COMMIT() asm volatile("cp.async.commit_group;" ::: "memory")
#define CP_WAIT(n)  asm volatile("cp.async.wait_group %0;" :: "n"(n) : "memory")

// branchless best-2; strict < + increasing-k order keeps first index on ties
#define UPD2(v0, i0, v1, i1, dv, kk) do { \
    bool _p0 = (dv) < (v0); \
    bool _p1 = (dv) < (v1); \
    (v1) = _p0 ? (v0) : (_p1 ? (dv) : (v1)); \
    (i1) = _p0 ? (i0) : (_p1 ? (kk) : (i1)); \
    (v0) = _p0 ? (dv) : (v0); \
    (i0) = _p0 ? (kk) : (i0); \
} while (0)

// merge two best-2 sets (values+indices), index tie-break
#define MERGE2(v0, i0, v1, i1, w0, j0, w1, j1) do { \
    bool _t = ((w0) < (v0)) || ((w0) == (v0) && (j0) < (i0)); \
    float _nv0 = _t ? (w0) : (v0); int _ni0 = _t ? (j0) : (i0); \
    float _c1v = _t ? (v0) : (w0); int _c1i = _t ? (i0) : (j0); \
    float _c2v = _t ? (w1) : (v1); int _c2i = _t ? (j1) : (i1); \
    bool _s = (_c1v < _c2v) || (_c1v == _c2v && _c1i < _c2i); \
    (v1) = _s ? _c1v : _c2v; (i1) = _s ? _c1i : _c2i; \
    (v0) = _nv0; (i0) = _ni0; \
} while (0)

// ---------------------------------------------------------------- L1: prep
__global__ void __launch_bounds__(256) vq_prep(const float* __restrict__ z,
                                               const float* __restrict__ cb) {
    int b = blockIdx.x, tid = threadIdx.x;
    int w = tid >> 5, lane = tid & 31;
    int row = b * 8 + w;
    bool isz = row < N_TOK;
    const float* src = isz ? z : cb;
    int r = isz ? row : row - N_TOK;

    float2 v = *(const float2*)&src[(size_t)r * ED + lane * 2];
    float sc = isz ? -2.0f : 1.0f;
    float m0 = sc * v.x, m1 = sc * v.y;
    __half h0 = __float2half_rn(m0), h1 = __float2half_rn(m1);
    __half2 hh; hh.x = h0; hh.y = h1;
    if (isz) {
        float l0 = m0 - __half2float(h0), l1 = m1 - __half2float(h1);
        __half2 ll; ll.x = __float2half_rn(l0); ll.y = __float2half_rn(l1);
        ((__half2*)d_zh)[(size_t)r * 32 + lane] = hh;
        ((__half2*)d_zl)[(size_t)r * 32 + lane] = ll;
    } else {
        ((__half2*)d_eh)[(size_t)r * 32 + lane] = hh;
    }

    float s = __fmaf_rn(v.x, v.x, v.y * v.y);
    #pragma unroll
    for (int o = 16; o; o >>= 1) s += __shfl_xor_sync(0xffffffffu, s, o);
    if (lane == 0) (isz ? d_sz : d_se)[r] = s;
}

// ---------------------------------------------------------------- L2/L3
__global__ void __launch_bounds__(256) vq_zero() {
    int i = blockIdx.x * 256 + threadIdx.x;
    if (i < NE) d_counts[i] = 0;
}
__global__ void __launch_bounds__(256) vq_aux() {
    if (blockIdx.x == 0 && threadIdx.x == 0) d_nflag = 0;
}

// ---------------------------------------------------------------- L4: main
static __device__ __forceinline__ void load_b(uint32_t sb, int ch, int buf) {
    int tid = threadIdx.x;
    size_t k0 = (size_t)ch * BN;
    uint32_t bh = sb + OFF_B + (uint32_t)buf * 16384u;
    #pragma unroll
    for (int p = 0; p < 2; p++) {
        int l = tid + p * NTHR;
        int row = l >> 3, seg = l & 7;
        uint32_t sw = swz((uint32_t)(row * 128 + seg * 16));
        size_t g = ((k0 + row) * ED + seg * 8) * 2;
        CP_ASYNC16(bh + sw, (const char*)d_eh + g);
    }
}

__global__ void __launch_bounds__(NTHR, 1) vq_main() {
    extern __shared__ char smem[];
    uint32_t sb = smem_u32(smem);
    const int tid = threadIdx.x;
    const int w = tid >> 5, lid = tid & 31;
    const int rowgrp = w & 7;       // rows [rowgrp*16, +16)
    const int nhalf = w >> 3;       // chunk codes [nhalf*64, +64)
    const int m0 = blockIdx.x * BM;

    #pragma unroll
    for (int p = 0; p < 2; p++) {
        int l = tid + p * NTHR;
        int row = l >> 3, seg = l & 7;
        uint32_t sw = swz((uint32_t)(row * 128 + seg * 16));
        size_t g = (((size_t)(m0 + row)) * ED + seg * 8) * 2;
        *(uint4*)(smem + OFF_A + sw)         = *(const uint4*)((const char*)d_zh + g);
        *(uint4*)(smem + OFF_A + 16384 + sw) = *(const uint4*)((const char*)d_zl + g);
    }
    float* ses = (float*)(smem + OFF_SES);
    for (int i = tid; i < NE; i += NTHR) ses[i] = d_se[i];
    __syncthreads();

    uint32_t ah[4][4], al[4][4];
    {
        int arow = rowgrp * 16 + (lid & 7) + ((lid >> 3) & 1) * 8;
        #pragma unroll
        for (int ks = 0; ks < 4; ks++) {
            uint32_t off = swz((uint32_t)(arow * 128 + ks * 32 + (lid >> 4) * 16));
            ldsm4(ah[ks][0], ah[ks][1], ah[ks][2], ah[ks][3], sb + OFF_A + off);
            ldsm4(al[ks][0], al[ks][1], al[ks][2], al[ks][3], sb + OFF_A + 16384u + off);
        }
    }

    float v00 = 3.4e38f, v01 = 3.4e38f, v10 = 3.4e38f, v11 = 3.4e38f;
    int   i00 = 0x7fffffff, i01 = 0x7fffffff, i10 = 0x7fffffff, i11 = 0x7fffffff;

    load_b(sb, 0, 0);
    CP_COMMIT();

    const int brow_l = (lid & 7) + ((lid >> 3) & 1) * 8;
    const int boff_l = (lid >> 4) * 16;

    for (int ch = 0; ch < NCH; ch++) {
        if (ch + 1 < NCH) { load_b(sb, ch + 1, (ch + 1) & 1); CP_COMMIT(); }
        if (ch + 1 < NCH) CP_WAIT(1); else CP_WAIT(0);
        __syncthreads();

        uint32_t bbase = sb + OFF_B + (uint32_t)((ch & 1) * 16384);

        #pragma unroll
        for (int nt2 = 0; nt2 < 4; nt2++) {
            int codebase = nhalf * 64 + nt2 * 16;
            float aE[4] = {0.f, 0.f, 0.f, 0.f};
            float aO[4] = {0.f, 0.f, 0.f, 0.f};
            #pragma unroll
            for (int ks = 0; ks < 4; ks++) {
                uint32_t sa = swz((uint32_t)((codebase + brow_l) * 128 + ks * 32 + boff_l));
                uint32_t h0, h1, h2, h3;
                ldsm4(h0, h1, h2, h3, bbase + sa);
                mma_f16(aE, ah[ks], h0, h2);
                mma_f16(aO, ah[ks], h1, h3);
                mma_f16(aE, al[ks], h0, h2);
                mma_f16(aO, al[ks], h1, h3);
            }
            int cE = codebase + 2 * (lid & 3);
            float2 sE = *(const float2*)&ses[ch * BN + cE];
            float2 sO = *(const float2*)&ses[ch * BN + cE + 8];
            int kg = ch * BN + cE;
            float dv;
            dv = __fadd_rn(aE[0], sE.x); UPD2(v00, i00, v01, i01, dv, kg);
            dv = __fadd_rn(aE[1], sE.y); UPD2(v00, i00, v01, i01, dv, kg + 1);
            dv = __fadd_rn(aO[0], sO.x); UPD2(v00, i00, v01, i01, dv, kg + 8);
            dv = __fadd_rn(aO[1], sO.y); UPD2(v00, i00, v01, i01, dv, kg + 9);
            dv = __fadd_rn(aE[2], sE.x); UPD2(v10, i10, v11, i11, dv, kg);
            dv = __fadd_rn(aE[3], sE.y); UPD2(v10, i10, v11, i11, dv, kg + 1);
            dv = __fadd_rn(aO[2], sO.x); UPD2(v10, i10, v11, i11, dv, kg + 8);
            dv = __fadd_rn(aO[3], sO.y); UPD2(v10, i10, v11, i11, dv, kg + 9);
        }
        __syncthreads();
    }

    // merge best-2 across the 4 quad threads (global best-2 per row-half)
    #pragma unroll
    for (int off = 2; off >= 1; off >>= 1) {
        float w0 = __shfl_down_sync(0xffffffffu, v00, off);
        int   j0 = __shfl_down_sync(0xffffffffu, i00, off);
        float w1 = __shfl_down_sync(0xffffffffu, v01, off);
        int   j1 = __shfl_down_sync(0xffffffffu, i01, off);
        MERGE2(v00, i00, v01, i01, w0, j0, w1, j1);
        w0 = __shfl_down_sync(0xffffffffu, v10, off);
        j0 = __shfl_down_sync(0xffffffffu, i10, off);
        w1 = __shfl_down_sync(0xffffffffu, v11, off);
        j1 = __shfl_down_sync(0xffffffffu, i11, off);
        MERGE2(v10, i10, v11, i11, w0, j0, w1, j1);
    }
    if ((lid & 3) == 0) {
        int t0 = m0 + rowgrp * 16 + (lid >> 2);
        ((float2*)d_c2v)[(size_t)t0 * 2 + nhalf]       = make_float2(v00, v01);
        ((int2*)  d_c2i)[(size_t)t0 * 2 + nhalf]       = make_int2(i00, i01);
        ((float2*)d_c2v)[(size_t)(t0 + 8) * 2 + nhalf] = make_float2(v10, v11);
        ((int2*)  d_c2i)[(size_t)(t0 + 8) * 2 + nhalf] = make_int2(i10, i11);
    }
}

// ---------------------------------------------------------------- L5: pick
__global__ void __launch_bounds__(256) vq_pick() {
    int t = blockIdx.x * 256 + threadIdx.x;
    float2 a  = ((const float2*)d_c2v)[(size_t)t * 2];
    float2 b  = ((const float2*)d_c2v)[(size_t)t * 2 + 1];
    int2   ai = ((const int2*)  d_c2i)[(size_t)t * 2];
    int2   bi = ((const int2*)  d_c2i)[(size_t)t * 2 + 1];
    float v0 = a.x, v1 = a.y; int i0 = ai.x, i1 = ai.y;
    MERGE2(v0, i0, v1, i1, b.x, bi.x, b.y, bi.y);
    d_win[t] = i0;                           // provisional (certified if gap wide)
    if (!(v1 - v0 > EPSW)) {
        int p = atomicAdd(&d_nflag, 1);
        d_flag[p] = t;
    }
}

// ---------------------------------------------------------------- L6: exact
// Batched exact (reference-chain) rescan for flagged tokens. 8 tokens/block,
// cb staged through smem (padded rows, conflict-free).
__global__ void __launch_bounds__(256) vq_exact(const float* __restrict__ z,
                                                const float* __restrict__ cb) {
    __shared__ float s_cb[64 * 65];
    __shared__ float s_z[8 * 64];
    int nf = d_nflag;
    int base = blockIdx.x * 8;
    if (base >= nf) return;
    int tid = threadIdx.x, w = tid >> 5, l = tid & 31;
    int t = (base + w < nf) ? d_flag[base + w] : -1;

    if (t >= 0) {
        s_z[w * 64 + l]      = z[(size_t)t * ED + l];
        s_z[w * 64 + 32 + l] = z[(size_t)t * ED + 32 + l];
    }
    float szt = (t >= 0) ? d_sz[t] : 0.f;
    float bv = 3.4e38f; int bi = 0x7fffffff;

    for (int chunk = 0; chunk < 64; chunk++) {
        __syncthreads();
        for (int i = tid; i < 4096; i += 256)
            s_cb[(i >> 6) * 65 + (i & 63)] = cb[(size_t)chunk * 4096 + i];
        __syncthreads();
        if (t >= 0) {
            const float* zr = &s_z[w * 64];
            #pragma unroll
            for (int p = 0; p < 2; p++) {
                int kc = p * 32 + l;
                int kg = chunk * 64 + kc;
                const float* cr = &s_cb[kc * 65];
                float dot = 0.f;
                #pragma unroll
                for (int d = 0; d < ED; d++) dot = __fmaf_rn(zr[d], cr[d], dot);
                float dv = __fmaf_rn(-2.0f, dot, __fadd_rn(szt, d_se[kg]));
                if (dv < bv) { bv = dv; bi = kg; }   // increasing k per lane
            }
        }
    }
    #pragma unroll
    for (int o = 16; o; o >>= 1) {
        float ov = __shfl_xor_sync(0xffffffffu, bv, o);
        int   oi = __shfl_xor_sync(0xffffffffu, bi, o);
        if (ov < bv || (ov == bv && oi < bi)) { bv = ov; bi = oi; }
    }
    if (t >= 0 && l == 0) d_win[t] = bi;
}

// ---------------------------------------------------------------- L7: write
__global__ void __launch_bounds__(256) vq_write(const float* __restrict__ z,
                                                const float* __restrict__ cb,
                                                float* __restrict__ out) {
    int t = (blockIdx.x * 256 + threadIdx.x) >> 5;
    int l = threadIdx.x & 31;
    int winner = d_win[t];

    if (l == 0) {
        out[OUT_IDX_OFF + t] = (float)winner;
        atomicAdd(&d_counts[winner], 1);
    }
    float lacc = 0.f;
    #pragma unroll
    for (int p = 0; p < 2; p++) {
        int d = l + p * 32;
        float zq = cb[(size_t)winner * ED + d];
        float zv = z[(size_t)t * ED + d];
        float tt = __fsub_rn(zq, zv);
        out[OUT_ZQ_OFF + (size_t)t * ED + d] = __fadd_rn(zv, tt);
        lacc = __fmaf_rn(tt, tt, lacc);
    }
    #pragma unroll
    for (int o = 16; o; o >>= 1) lacc += __shfl_xor_sync(0xffffffffu, lacc, o);
    if (l == 0) d_losstok[t] = lacc;
}

// ---------------------------------------------------------------- L8: finalize
__global__ void __launch_bounds__(1024) vq_finalize(float* __restrict__ out) {
    __shared__ double sh[1024];
    int tid = threadIdx.x;
    double s = 0.0;
    for (int i = tid; i < N_TOK; i += 1024) s += (double)d_losstok[i];
    sh[tid] = s;
    __syncthreads();
    #pragma unroll
    for (int st = 512; st > 0; st >>= 1) {
        if (tid < st) sh[tid] += sh[tid + st];
        __syncthreads();
    }
    if (tid == 0)
        out[0] = (float)(1.25 * sh[0] / (double)((size_t)N_TOK * ED));
    __syncthreads();

    double h = 0.0;
    for (int i = tid; i < NE; i += 1024) {
        float em = (float)d_counts[i] / (float)N_TOK;
        h += (double)(em * logf(em + 1e-10f));
    }
    sh[tid] = h;
    __syncthreads();
    #pragma unroll
    for (int st = 512; st > 0; st >>= 1) {
        if (tid < st) sh[tid] += sh[tid + st];
        __syncthreads();
    }
    if (tid == 0)
        out[OUT_PERP_OFF] = expf(-(float)sh[0]);
}

// ---------------------------------------------------------------- launch
extern "C" void kernel_launch(void* const* d_in, const int* in_sizes, int n_in,
                              void* d_out, int out_size) {
    const float* z  = (const float*)d_in[0];
    const float* cb = (const float*)d_in[1];
    float* out = (float*)d_out;

    cudaFuncSetAttribute(vq_main, cudaFuncAttributeMaxDynamicSharedMemorySize, SMEM_MAIN);

    vq_prep<<<2560, 256>>>(z, cb);          // L1
    vq_zero<<<16, 256>>>();                 // L2
    vq_aux<<<1, 256>>>();                   // L3
    vq_main<<<NBLK, NTHR, SMEM_MAIN>>>();   // L4  <- ncu capture slot
    vq_pick<<<N_TOK / 256, 256>>>();        // L5
    vq_exact<<<2048, 256>>>(z, cb);         // L6
    vq_write<<<N_TOK / 8, 256>>>(z, cb, out); // L7
    vq_finalize<<<1, 1024>>>(out);          // L8
}